// round 8
// baseline (speedup 1.0000x reference)
#include <cuda_runtime.h>
#include <cstdint>

#define NN     1024
#define NINP   256
#define NOUTP  256
#define NBAT   8192
#define MAXF   96     // far pairs cap per row (max ~68 stat)
#define IMAX   16     // intra-block pairs cap
#define THREADS 512   // 16 warps; 32 batch columns (1 float per lane)

__device__ int2 g_pairs[NN * MAXF];   // far: {col*33 (float idx), bits(w)}
__device__ int2 g_intra[NN * IMAX];   // intra-block pairs (hidden rows only)
__device__ int2 g_meta [NN];          // {far count, bits(bias)}
__device__ int  g_icnt [NN];
__device__ int  g_ordic[16 * 32];     // per block: node | (icnt<<8), level-sorted
__device__ int  g_lst  [16 * 34];     // per block: level start offsets

// ============================================================================
// Build 1: 8 warps/block, one row per warp, coalesced float4 reads.
// Pair order = (chunk, q, lane) interleave: deterministic, order-free consumers.
// ============================================================================
__global__ void build_csr(const float* __restrict__ W, const float* __restrict__ b)
{
    int row  = blockIdx.x * 8 + (threadIdx.x >> 5);
    int lane = threadIdx.x & 31;
    int fb;
    if (row < NINP)            fb = 0;
    else if (row < NN - NOUTP) fb = NINP + (((row - NINP) >> 5) << 5);
    else                       fb = NN;
    int fc = 0, ic = 0;
    unsigned lt = (1u << lane) - 1u;
    const float4* wr = reinterpret_cast<const float4*>(W + (size_t)row * NN);
    #pragma unroll
    for (int m = 0; m < 8; ++m) {
        float4 v = __ldg(wr + m * 32 + lane);
        int c0 = m * 128 + lane * 4;
        #pragma unroll
        for (int q = 0; q < 4; ++q) {
            float wv = (q == 0) ? v.x : (q == 1) ? v.y : (q == 2) ? v.z : v.w;
            int col = c0 + q;
            bool nz = (wv != 0.0f);
            unsigned bf = __ballot_sync(~0u, nz && col <  fb);
            unsigned bi = __ballot_sync(~0u, nz && col >= fb);
            if (nz) {
                if (col < fb) {
                    int p = fc + __popc(bf & lt);
                    if (p < MAXF) g_pairs[row*MAXF+p] = make_int2(col*33, __float_as_int(wv));
                } else {
                    int p = ic + __popc(bi & lt);
                    if (p < IMAX) g_intra[row*IMAX+p] = make_int2(col*33, __float_as_int(wv));
                }
            }
            fc += __popc(bf); ic += __popc(bi);
        }
    }
    for (int t = ic + lane; t < IMAX; t += 32) g_intra[row*IMAX+t] = make_int2(0,0);
    if (lane == 0) {
        g_meta[row] = make_int2(fc < MAXF ? fc : MAXF, __float_as_int(b[row]));
        g_icnt[row] = ic < IMAX ? ic : IMAX;
    }
}

// ============================================================================
// Build 2: per hidden block, dependency levels of the 32 nodes.
// ============================================================================
__global__ void build_levels()
{
    int blk = blockIdx.x, n = threadIdx.x;
    int base = NINP + blk * 32;
    int row = base + n;
    int ic = g_icnt[row];
    unsigned mymask = 0;
    for (int s = 0; s < ic; ++s) {
        int d = g_intra[row * IMAX + s].x / 33 - base;
        mymask |= 1u << d;
    }
    int lvl = -1;
    unsigned done = 0;
    for (int it = 0; it < 32; ++it) {
        bool rdy = (lvl < 0) && ((mymask & ~done) == 0);
        unsigned bal = __ballot_sync(~0u, rdy);
        if (rdy) lvl = it;
        done |= bal;
        if (done == 0xffffffffu) break;
    }
    unsigned lt = (1u << n) - 1u;
    int run = 0, pos = 0;
    for (int L = 0; L < 32; ++L) {
        unsigned bal = __ballot_sync(~0u, lvl == L);
        if (lvl == L) pos = run + __popc(bal & lt);
        if (n == 0 && L < 34) g_lst[blk * 34 + L] = (run < 32) ? run : 32;
        run += __popc(bal);
    }
    if (n < 2) g_lst[blk * 34 + 32 + n] = 32;
    g_ordic[blk * 32 + pos] = n | (ic << 8);
}

// ============================================================================
// Main kernel: 32 batch cols/CTA, smem 109,960B -> 2 CTAs/SM (occ 50%).
//   z    [768][33] float @0       101376
//   acc  [32*33]  float  @101376    4224
//   ipb  [32*16]  int2   @105600    4096
//   sord [32]     int    @109696     128
//   slst [34]     int    @109824     136   total 109960
// ============================================================================
extern __shared__ char smraw[];

__device__ __forceinline__ float tanhfast(float v) {
    float e = __expf(v + v);
    return 1.0f - __fdividef(2.0f, e + 1.0f);
}

__device__ __forceinline__ void afar_row(int row, int n, float* acc,
                                         int lane, const float* z)
{
    int2 mt = __ldg(&g_meta[row]);
    int cnt = mt.x;
    float x0 = __int_as_float(mt.y), x1 = 0.f;
    const int4* p4 = (const int4*)(g_pairs + (size_t)row * MAXF);
    int h = cnt >> 1;
    #pragma unroll 8
    for (int q = 0; q < h; ++q) {
        int4 pp = __ldg(p4 + q);
        x0 = fmaf(__int_as_float(pp.y), z[pp.x + lane], x0);
        x1 = fmaf(__int_as_float(pp.w), z[pp.z + lane], x1);
    }
    if (cnt & 1) {
        int2 pp = __ldg((const int2*)p4 + (cnt - 1));
        x0 = fmaf(__int_as_float(pp.y), z[pp.x + lane], x0);
    }
    acc[n*33 + lane] = x0 + x1;
}

__global__ void __launch_bounds__(THREADS, 2)
dagnn_main(const float* __restrict__ x, float* __restrict__ out)
{
    float* z    = (float*)smraw;
    float* acc  = (float*)(smraw + 101376);
    int2*  ipb  = (int2*) (smraw + 105600);
    int*   sord = (int*)  (smraw + 109696);
    int*   slst = (int*)  (smraw + 109824);

    int tid = threadIdx.x, w = tid >> 5, lane = tid & 31;
    int b0 = blockIdx.x * 32;

    // transpose x into z[node][col]
    #pragma unroll
    for (int it = 0; it < 16; ++it) {
        int t = tid + it * THREADS;
        int n = t & 255, c = t >> 8;
        z[n * 33 + c] = x[(size_t)(b0 + c) * NINP + n];
    }
    __syncthreads();

    // ---------------- hidden blocks ----------------
    for (int k = 0; k < 16; ++k) {
        int base = NINP + k * 32;

        // stage intra pairs + order + level starts (overlaps far phase)
        if (tid < 256)
            ((int4*)ipb)[tid] = __ldg((const int4*)(g_intra + (size_t)base * IMAX) + tid);
        else if (tid < 288)
            sord[tid - 256] = __ldg(&g_ordic[k * 32 + tid - 256]);
        else if (tid < 322)
            slst[tid - 288] = __ldg(&g_lst[k * 34 + tid - 288]);

        // far phase: 16 warps, rows (w, w+16)
        afar_row(base + w,      w,      acc, lane, z);
        afar_row(base + w + 16, w + 16, acc, lane, z);
        __syncthreads();

        // level-parallel intra + tanh
        for (int L = 0; slst[L] < 32; ++L) {
            for (int j = slst[L] + w; j < slst[L + 1]; j += 16) {
                int oi = sord[j];
                int n  = oi & 255;
                int ic = oi >> 8;
                float v = acc[n*33 + lane];
                const int2* q = ipb + n * IMAX;
                for (int s = 0; s < ic; ++s) {
                    int2 p = q[s];
                    v = fmaf(__int_as_float(p.y), z[p.x + lane], v);
                }
                z[(base + n) * 33 + lane] = tanhfast(v);
            }
            __syncthreads();
        }
        __syncthreads();
    }

    // ---------------- output epilogue: 8 chunks, fully parallel ----------------
    for (int ko = 0; ko < 8; ++ko) {
        int base = NN - NOUTP + ko * 32;
        afar_row(base + w,      w,      acc, lane, z);
        afar_row(base + w + 16, w + 16, acc, lane, z);
        __syncthreads();
        int goff = base - (NN - NOUTP);
        #pragma unroll
        for (int rr = 0; rr < 2; ++rr) {
            int c = (tid >> 5) + 16 * rr;     // batch col (same per warp)
            out[(size_t)(b0 + c) * NOUTP + goff + lane] = acc[lane*33 + c];
        }
        __syncthreads();
    }
}

// ============================================================================
extern "C" void kernel_launch(void* const* d_in, const int* in_sizes, int n_in,
                              void* d_out, int out_size)
{
    const float* x = nullptr; const float* W = nullptr; const float* b = nullptr;
    for (int i = 0; i < n_in; ++i) {
        if      (in_sizes[i] == NBAT * NINP) x = (const float*)d_in[i];
        else if (in_sizes[i] == NN * NN)     W = (const float*)d_in[i];
        else if (in_sizes[i] == NN)          b = (const float*)d_in[i];
    }

    build_csr<<<NN / 8, 256>>>(W, b);
    build_levels<<<16, 32>>>();

    int smem_bytes = 109960;
    cudaFuncSetAttribute(dagnn_main,
                         cudaFuncAttributeMaxDynamicSharedMemorySize, smem_bytes);
    dagnn_main<<<NBAT / 32, THREADS, smem_bytes>>>(x, (float*)d_out);
}

// round 10
// speedup vs baseline: 1.1364x; 1.1364x over previous
#include <cuda_runtime.h>
#include <cstdint>

#define NN     1024
#define NINP   256
#define NOUTP  256
#define NBAT   8192
#define MAXF   96     // far pairs cap per row
#define BPMAX  16     // near+intra pairs cap (mean ~3.2)
#define THREADS 512   // 16 warps; 64 batch cols (float2 per lane)

__device__ int2 g_far [NN * MAXF];    // {col*33 (float2 idx), bits(w)}
__device__ int2 g_bp  [NN * BPMAX];   // cols >= base-32 (near + intra)
__device__ int2 g_meta[NN];           // {far count, bits(bias)}
__device__ int  g_bcnt[NN];
__device__ int  g_ord [16 * 32];      // node | (bcnt<<8), level-sorted
__device__ int  g_lst [16 * 34];      // level start offsets (sentinel 32)

// ============================================================================
// Build 1: rows 256..1023 only (input rows are all-zero). 8 warps/block.
// fb2 is a 32-multiple -> far/bp decision is uniform per 32-col chunk.
// ============================================================================
__global__ void build_csr(const float* __restrict__ W, const float* __restrict__ b)
{
    int row  = NINP + blockIdx.x * 8 + (threadIdx.x >> 5);
    int lane = threadIdx.x & 31;
    bool isOut = (row >= NN - NOUTP);
    int fb2  = isOut ? NN : ((row & ~31) - 32);
    int mmax = min(row >> 5, 23);
    int fc = 0, bc = 0;
    unsigned lt = (1u << lane) - 1u;
    for (int m = 0; m <= mmax; ++m) {
        int col = m * 32 + lane;
        float wv = __ldg(&W[(size_t)row * NN + col]);
        unsigned bal = __ballot_sync(~0u, wv != 0.0f);
        if (m * 32 < fb2) {
            if (wv != 0.0f) {
                int p = fc + __popc(bal & lt);
                if (p < MAXF) g_far[row*MAXF+p] = make_int2(col*33, __float_as_int(wv));
            }
            fc += __popc(bal);
        } else {
            if (wv != 0.0f) {
                int p = bc + __popc(bal & lt);
                if (p < BPMAX) g_bp[row*BPMAX+p] = make_int2(col*33, __float_as_int(wv));
            }
            bc += __popc(bal);
        }
    }
    for (int t = bc + lane; t < BPMAX; t += 32) g_bp[row*BPMAX+t] = make_int2(0,0);
    if (lane == 0) {
        g_meta[row] = make_int2(fc < MAXF ? fc : MAXF, __float_as_int(b[row]));
        g_bcnt[row] = bc < BPMAX ? bc : BPMAX;
    }
}

// ============================================================================
// Build 2: per hidden block, dependency levels from IN-BLOCK bp sources only.
// ============================================================================
__global__ void build_levels()
{
    int blk = blockIdx.x, n = threadIdx.x;
    int base = NINP + blk * 32;
    int row = base + n;
    int bc = g_bcnt[row];
    unsigned mymask = 0;
    for (int s = 0; s < bc; ++s) {
        int col = g_bp[row * BPMAX + s].x / 33;
        int d = col - base;
        if (d >= 0) mymask |= 1u << d;
    }
    int lvl = -1;
    unsigned done = 0;
    for (int it = 0; it < 32; ++it) {
        bool rdy = (lvl < 0) && ((mymask & ~done) == 0);
        unsigned bal = __ballot_sync(~0u, rdy);
        if (rdy) lvl = it;
        done |= bal;
        if (done == 0xffffffffu) break;
    }
    unsigned lt = (1u << n) - 1u;
    int run = 0, pos = 0;
    for (int L = 0; L < 32; ++L) {
        unsigned bal = __ballot_sync(~0u, lvl == L);
        if (lvl == L) pos = run + __popc(bal & lt);
        if (n == 0 && L < 34) g_lst[blk * 34 + L] = (run < 32) ? run : 32;
        run += __popc(bal);
    }
    if (n < 2) g_lst[blk * 34 + 32 + n] = 32;
    g_ord[blk * 32 + pos] = n | (bc << 8);
}

// ============================================================================
// Main. smem (bytes):
//   z2   float2[768][33]  @0        202752
//   acc  float2[2][32*33] @202752    16896
//   bpb  int2 [2][32*16]  @219648     8192
//   sord int  [2][32]     @227840      256
//   slst int  [2][34]     @228096      272   total 228368
// ============================================================================
extern __shared__ char smraw[];

__device__ __forceinline__ float tanhfast(float v) {
    float e = __expf(v + v);
    return 1.0f - __fdividef(2.0f, e + 1.0f);
}

__device__ __forceinline__ void afar2_row(int row, int n, float2* acc,
                                          int lane, const float2* z2)
{
    int2 mt = __ldg(&g_meta[row]);
    int cnt = mt.x;
    float bias = __int_as_float(mt.y);
    float xA0 = bias, xB0 = bias, xA1 = 0.f, xB1 = 0.f;
    const int4* p4 = (const int4*)(g_far + (size_t)row * MAXF);
    int h = cnt >> 1;
    #pragma unroll 8
    for (int q = 0; q < h; ++q) {
        int4 pp = __ldg(p4 + q);
        float2 za = z2[pp.x + lane];
        float2 zb = z2[pp.z + lane];
        float w0 = __int_as_float(pp.y), w1 = __int_as_float(pp.w);
        xA0 = fmaf(w0, za.x, xA0); xB0 = fmaf(w0, za.y, xB0);
        xA1 = fmaf(w1, zb.x, xA1); xB1 = fmaf(w1, zb.y, xB1);
    }
    if (cnt & 1) {
        int2 pp = __ldg((const int2*)p4 + (cnt - 1));
        float2 za = z2[pp.x + lane];
        float w0 = __int_as_float(pp.y);
        xA0 = fmaf(w0, za.x, xA0); xB0 = fmaf(w0, za.y, xB0);
    }
    acc[n * 33 + lane] = make_float2(xA0 + xA1, xB0 + xB1);
}

__device__ __forceinline__ void stage_block(int blk, int buf, int2* bpb,
                                            int* sord, int* slst, int st)
{
    const int4* src = (const int4*)(g_bp + (size_t)(NINP + blk * 32) * BPMAX);
    int4* dst = (int4*)(bpb + buf * (32 * BPMAX));
    dst[st]       = __ldg(src + st);
    dst[st + 128] = __ldg(src + st + 128);
    if (st < 32)               sord[buf * 32 + st]      = __ldg(&g_ord[blk * 32 + st]);
    if (st >= 64 && st < 98)   slst[buf * 34 + st - 64] = __ldg(&g_lst[blk * 34 + st - 64]);
}

__global__ void __launch_bounds__(THREADS, 1)
dagnn_main(const float* __restrict__ x, float* __restrict__ out)
{
    float2* z2   = (float2*)smraw;
    float2* acc  = (float2*)(smraw + 202752);
    int2*   bpb  = (int2*)  (smraw + 219648);
    int*    sord = (int*)   (smraw + 227840);
    int*    slst = (int*)   (smraw + 228096);

    int tid = threadIdx.x, w = tid >> 5, lane = tid & 31;
    int b0 = blockIdx.x * 64;
    float* zf = (float*)z2;

    // fill z2: coalesced LDG, 2-way-conflict STS (stride 66 floats)
    #pragma unroll
    for (int it = 0; it < 32; ++it) {
        int t = tid + it * THREADS;
        int n = t & 255, c = t >> 8;
        zf[n * 66 + c] = x[(size_t)(b0 + c) * NINP + n];
    }

    // prologue: stage block 0 (warps 4..7) + far(0) by all 16 warps
    if (w >= 4 && w < 8) stage_block(0, 0, bpb, sord, slst, tid - 128);
    __syncthreads();
    afar2_row(NINP + w,      w,      acc, lane, z2);
    afar2_row(NINP + w + 16, w + 16, acc, lane, z2);
    __syncthreads();

    // ---------------- 16 pipelined iterations ----------------
    for (int k = 0; k < 16; ++k) {
        if (w >= 4) {
            // far warps: stage bp(k+1) + compute far(k+1). Idle at k=15
            // (output chunk 0 must NOT read block 15 while it's being written).
            if (k < 15) {
                if (w < 8) stage_block(k + 1, (k + 1) & 1, bpb, sord, slst, tid - 128);
                int nb = NINP + (k + 1) * 32;
                float2* a = acc + ((k + 1) & 1) * (32 * 33);
                #pragma unroll
                for (int jj = 0; jj < 3; ++jj) {
                    int r = (w - 4) + 12 * jj;
                    if (r < 32) afar2_row(nb + r, r, a, lane, z2);
                }
            }
        } else {
            // level warps (0..3): bp + tanh for block k, level by level
            int buf = k & 1;
            int base = NINP + k * 32;
            const int2* bq = bpb + buf * (32 * BPMAX);
            const int*  so = sord + buf * 32;
            const int*  sl = slst + buf * 34;
            float2* a = acc + buf * (32 * 33);
            for (int L = 0; sl[L] < 32; ++L) {
                for (int j = sl[L] + w; j < sl[L + 1]; j += 4) {
                    int oi = so[j];
                    int n  = oi & 255;
                    int bc = oi >> 8;
                    float2 v = a[n * 33 + lane];
                    const int2* q = bq + n * BPMAX;
                    for (int s = 0; s < bc; ++s) {
                        int2 p = q[s];
                        float2 zz = z2[p.x + lane];
                        float wv = __int_as_float(p.y);
                        v.x = fmaf(wv, zz.x, v.x);
                        v.y = fmaf(wv, zz.y, v.y);
                    }
                    z2[(base + n) * 33 + lane] = make_float2(tanhfast(v.x), tanhfast(v.y));
                }
                asm volatile("bar.sync 1, 128;" ::: "memory");
            }
        }
        __syncthreads();
    }

    // ---------------- output epilogue ----------------
    // chunk 0 by all warps (z fully finalized now)
    afar2_row(768 + w,      w,      acc, lane, z2);
    afar2_row(768 + w + 16, w + 16, acc, lane, z2);
    __syncthreads();

    // writeout(j) || compute(j+1)
    for (int j = 0; j < 8; ++j) {
        const float* af = (const float*)(acc + (j & 1) * (32 * 33));
        #pragma unroll
        for (int cc = 0; cc < 4; ++cc) {
            int c = w * 4 + cc;
            out[(size_t)(b0 + c) * NOUTP + j * 32 + lane] = af[lane * 66 + c];
        }
        if (j < 7) {
            int base = 768 + (j + 1) * 32;
            float2* a = acc + ((j + 1) & 1) * (32 * 33);
            afar2_row(base + w,      w,      a, lane, z2);
            afar2_row(base + w + 16, w + 16, a, lane, z2);
        }
        __syncthreads();
    }
}

// ============================================================================
extern "C" void kernel_launch(void* const* d_in, const int* in_sizes, int n_in,
                              void* d_out, int out_size)
{
    const float* x = nullptr; const float* W = nullptr; const float* b = nullptr;
    for (int i = 0; i < n_in; ++i) {
        if      (in_sizes[i] == NBAT * NINP) x = (const float*)d_in[i];
        else if (in_sizes[i] == NN * NN)     W = (const float*)d_in[i];
        else if (in_sizes[i] == NN)          b = (const float*)d_in[i];
    }

    build_csr<<<(NN - NINP) / 8, 256>>>(W, b);
    build_levels<<<16, 32>>>();

    int smem_bytes = 228368;
    cudaFuncSetAttribute(dagnn_main,
                         cudaFuncAttributeMaxDynamicSharedMemorySize, smem_bytes);
    dagnn_main<<<NBAT / 64, THREADS, smem_bytes>>>(x, (float*)d_out);
}

// round 11
// speedup vs baseline: 1.2152x; 1.0694x over previous
#include <cuda_runtime.h>
#include <cstdint>

#define NN     1024
#define NINP   256
#define NOUTP  256
#define NBAT   8192
#define MAXF   96      // padded far cap per row (intermediate)
#define IMAX   12      // intra-only cap per row (mean 0.8, P(>12) ~ 1e-8)
#define CAP    1536    // compact pairs per 32-row block (mean ~1100, 10+ sigma)
#define NBLK   24      // 16 hidden + 8 output
#define THREADS 512

__device__ int2 g_far  [NN * MAXF];    // padded per-row far pairs {col*33, w}
__device__ int2 g_intra[NN * IMAX];    // intra-block pairs
__device__ int2 g_meta [NN];           // {far count, bits(bias)}
__device__ int  g_icnt [NN];
__device__ int2 g_cpack[NBLK * CAP];   // compact per-block far stream
__device__ int  g_coff [NBLK * 33];    // per-block row offsets (+total)
__device__ int  g_ord  [16 * 32];      // node | (icnt<<8), level-sorted
__device__ int  g_lst  [16 * 34];      // level starts (sentinel 32)

// ============================================================================
// Build 1: rows 256..1023, one warp/row, float4 coalesced, row-bounded.
// far = col < (row & ~31) [hidden] or all [output]; intra = rest.
// ============================================================================
__global__ void build_csr(const float* __restrict__ W, const float* __restrict__ b)
{
    int row  = NINP + blockIdx.x * 8 + (threadIdx.x >> 5);
    int lane = threadIdx.x & 31;
    int fb   = (row >= NN - NOUTP) ? NN : (row & ~31);
    int m4max = (row + 127) >> 7;          // chunks of 128 cols
    int fc = 0, ic = 0;
    unsigned lt = (1u << lane) - 1u;
    const float4* wr = reinterpret_cast<const float4*>(W + (size_t)row * NN);
    for (int m = 0; m < m4max; ++m) {
        float4 v = __ldg(wr + m * 32 + lane);
        int c0 = m * 128 + lane * 4;
        #pragma unroll
        for (int q = 0; q < 4; ++q) {
            float wv = (q == 0) ? v.x : (q == 1) ? v.y : (q == 2) ? v.z : v.w;
            int col = c0 + q;
            bool nz = (wv != 0.0f);
            unsigned bf = __ballot_sync(~0u, nz && col <  fb);
            unsigned bi = __ballot_sync(~0u, nz && col >= fb);
            if (nz) {
                if (col < fb) {
                    int p = fc + __popc(bf & lt);
                    if (p < MAXF) g_far[row*MAXF+p] = make_int2(col*33, __float_as_int(wv));
                } else {
                    int p = ic + __popc(bi & lt);
                    if (p < IMAX) g_intra[row*IMAX+p] = make_int2(col*33, __float_as_int(wv));
                }
            }
            fc += __popc(bf); ic += __popc(bi);
        }
    }
    if (lane == 0) {
        g_meta[row] = make_int2(fc < MAXF ? fc : MAXF, __float_as_int(b[row]));
        g_icnt[row] = ic < IMAX ? ic : IMAX;
    }
}

// ============================================================================
// Build 2: compact per-block far stream + prefix offsets. One warp per block.
// ============================================================================
__global__ void build_compact()
{
    int blk = blockIdx.x, lane = threadIdx.x;
    int base = NINP + blk * 32;
    int cnt = g_meta[base + lane].x;
    int v = cnt;
    #pragma unroll
    for (int d = 1; d < 32; d <<= 1) {
        int t = __shfl_up_sync(~0u, v, d);
        if (lane >= d) v += t;
    }
    int excl = v - cnt;
    g_coff[blk * 33 + lane] = excl;
    if (lane == 31) g_coff[blk * 33 + 32] = (v < CAP) ? v : CAP;
    for (int n = 0; n < 32; ++n) {
        int o = __shfl_sync(~0u, excl, n);
        int c = __shfl_sync(~0u, cnt,  n);
        if (o + c > CAP) c = CAP - o > 0 ? CAP - o : 0;
        const int2* src = g_far + (size_t)(base + n) * MAXF;
        for (int t = lane; t < c; t += 32)
            g_cpack[blk * CAP + o + t] = src[t];
    }
}

// ============================================================================
// Build 3: dependency levels per hidden block (intra-only).
// ============================================================================
__global__ void build_levels()
{
    int blk = blockIdx.x, n = threadIdx.x;
    int base = NINP + blk * 32;
    int row = base + n;
    int ic = g_icnt[row];
    unsigned mymask = 0;
    for (int s = 0; s < ic; ++s) {
        int d = g_intra[row * IMAX + s].x / 33 - base;
        if (d >= 0) mymask |= 1u << d;
    }
    int lvl = -1;
    unsigned done = 0;
    for (int it = 0; it < 32; ++it) {
        bool rdy = (lvl < 0) && ((mymask & ~done) == 0);
        unsigned bal = __ballot_sync(~0u, rdy);
        if (rdy) lvl = it;
        done |= bal;
        if (done == 0xffffffffu) break;
    }
    unsigned lt = (1u << n) - 1u;
    int run = 0, pos = 0;
    for (int L = 0; L < 32; ++L) {
        unsigned bal = __ballot_sync(~0u, lvl == L);
        if (lvl == L) pos = run + __popc(bal & lt);
        if (n == 0 && L < 34) g_lst[blk * 34 + L] = (run < 32) ? run : 32;
        run += __popc(bal);
    }
    if (n < 2) g_lst[blk * 34 + 32 + n] = 32;
    g_ord[blk * 32 + pos] = n | (ic << 8);
}

// ============================================================================
// Main. smem (bytes):
//   z2     float2[768][33] @0        202752
//   acc    float2[32*33]   @202752     8448
//   cpairs int2[1536]      @211200    12288
//   coff   int[33]         @223488      136
//   ipb    int2[32*12]     @223624     3072
//   sord   int[32]         @226696      128
//   slst   int[34]         @226824      136    total 226960
// ============================================================================
extern __shared__ char smraw[];

__device__ __forceinline__ float tanhfast(float v) {
    float e = __expf(v + v);
    return 1.0f - __fdividef(2.0f, e + 1.0f);
}

__global__ void __launch_bounds__(THREADS, 1)
dagnn_main(const float* __restrict__ x, float* __restrict__ out)
{
    float2* z2    = (float2*)smraw;
    float2* acc   = (float2*)(smraw + 202752);
    int2*   cpair = (int2*)  (smraw + 211200);
    int*    coff  = (int*)   (smraw + 223488);
    int2*   ipb   = (int2*)  (smraw + 223624);
    int*    sord  = (int*)   (smraw + 226696);
    int*    slst  = (int*)   (smraw + 226824);

    int tid = threadIdx.x, w = tid >> 5, lane = tid & 31;
    int b0 = blockIdx.x * 64;
    float* zf = (float*)z2;

    // ---- prefetch registers for next block's staged data ----
    int2 p0, p1, p2, ib;
    int  aux = 0;

    // prefetch block 0
    {
        const int2* cp = g_cpack;                       // blk 0
        p0 = __ldg(cp + tid); p1 = __ldg(cp + 512 + tid); p2 = __ldg(cp + 1024 + tid);
        if (tid < 384)            ib  = __ldg(&g_intra[(size_t)NINP * IMAX + tid]);
        else if (tid < 416)       aux = __ldg(&g_ord[tid - 384]);
        else if (tid < 450)       aux = __ldg(&g_lst[tid - 416]);
        else if (tid < 483)       aux = __ldg(&g_coff[tid - 450]);
    }

    // fill z2 with inputs (coalesced LDG, 2-way STS conflict)
    #pragma unroll
    for (int it = 0; it < 32; ++it) {
        int t = tid + it * THREADS;
        int n = t & 255, c = t >> 8;
        zf[n * 66 + c] = x[(size_t)(b0 + c) * NINP + n];
    }

    for (int k = 0; k < NBLK; ++k) {
        bool hid = (k < 16);
        int base = NINP + k * 32;

        // ---- commit staged data for block k ----
        __syncthreads();                 // protect smem from late readers
        cpair[tid] = p0; cpair[512 + tid] = p1; cpair[1024 + tid] = p2;
        if (tid < 384)      { if (hid) ipb[tid] = ib; }
        else if (tid < 416) { if (hid) sord[tid - 384] = aux; }
        else if (tid < 450) { if (hid) slst[tid - 416] = aux; }
        else if (tid < 483) { coff[tid - 450] = aux; }
        __syncthreads();

        // ---- prefetch block k+1 (completes during far+levels) ----
        if (k + 1 < NBLK) {
            int nb = k + 1;
            bool nhid = (nb < 16);
            const int2* cp = g_cpack + (size_t)nb * CAP;
            p0 = __ldg(cp + tid); p1 = __ldg(cp + 512 + tid); p2 = __ldg(cp + 1024 + tid);
            if (tid < 384)      { if (nhid) ib  = __ldg(&g_intra[(size_t)(NINP + nb*32) * IMAX + tid]); }
            else if (tid < 416) { if (nhid) aux = __ldg(&g_ord[nb * 32 + tid - 384]); }
            else if (tid < 450) { if (nhid) aux = __ldg(&g_lst[nb * 34 + tid - 416]); }
            else if (tid < 483) { aux = __ldg(&g_coff[nb * 33 + tid - 450]); }
        }

        // ---- far phase: warp w handles rows 2w, 2w+1; pairs from smem ----
        #pragma unroll
        for (int rr = 0; rr < 2; ++rr) {
            int n = 2 * w + rr;
            int row = base + n;
            int bb = __ldg(&g_meta[row]).y;           // bias (added at end)
            int s = coff[n], e = coff[n + 1];
            float a0 = 0.f, a1 = 0.f, a2 = 0.f, a3 = 0.f;
            float c0 = 0.f, c1 = 0.f, c2 = 0.f, c3 = 0.f;
            int i = s;
            for (; i + 4 <= e; i += 4) {
                int2 q0 = cpair[i], q1 = cpair[i+1], q2 = cpair[i+2], q3 = cpair[i+3];
                float2 z0 = z2[q0.x + lane], z1v = z2[q1.x + lane];
                float2 z2v = z2[q2.x + lane], z3 = z2[q3.x + lane];
                float w0 = __int_as_float(q0.y), w1 = __int_as_float(q1.y);
                float w2 = __int_as_float(q2.y), w3 = __int_as_float(q3.y);
                a0 = fmaf(w0, z0.x, a0);  c0 = fmaf(w0, z0.y, c0);
                a1 = fmaf(w1, z1v.x, a1); c1 = fmaf(w1, z1v.y, c1);
                a2 = fmaf(w2, z2v.x, a2); c2 = fmaf(w2, z2v.y, c2);
                a3 = fmaf(w3, z3.x, a3);  c3 = fmaf(w3, z3.y, c3);
            }
            for (; i < e; ++i) {
                int2 q = cpair[i];
                float2 zz = z2[q.x + lane];
                float wv = __int_as_float(q.y);
                a0 = fmaf(wv, zz.x, a0); c0 = fmaf(wv, zz.y, c0);
            }
            float bias = __int_as_float(bb);
            acc[n * 33 + lane] = make_float2(bias + (a0 + a1) + (a2 + a3),
                                             bias + (c0 + c1) + (c2 + c3));
        }
        __syncthreads();

        if (hid) {
            // ---- level-parallel intra + tanh (16 warps) ----
            for (int L = 0; slst[L] < 32; ++L) {
                for (int j = slst[L] + w; j < slst[L + 1]; j += 16) {
                    int oi = sord[j];
                    int n  = oi & 255;
                    int ic = oi >> 8;
                    float2 v = acc[n * 33 + lane];
                    const int2* q = ipb + n * IMAX;
                    for (int s = 0; s < ic; ++s) {
                        int2 p = q[s];
                        float2 zz = z2[p.x + lane];
                        float wv = __int_as_float(p.y);
                        v.x = fmaf(wv, zz.x, v.x);
                        v.y = fmaf(wv, zz.y, v.y);
                    }
                    z2[(base + n) * 33 + lane] = make_float2(tanhfast(v.x), tanhfast(v.y));
                }
                __syncthreads();
            }
        } else {
            // ---- output writeout: acc -> gmem, coalesced ----
            int goff = (k - 16) * 32;
            const float* af = (const float*)acc;
            #pragma unroll
            for (int cc = 0; cc < 4; ++cc) {
                int c = w * 4 + cc;
                out[(size_t)(b0 + c) * NOUTP + goff + lane] = af[lane * 66 + c];
            }
            __syncthreads();
        }
    }
}

// ============================================================================
extern "C" void kernel_launch(void* const* d_in, const int* in_sizes, int n_in,
                              void* d_out, int out_size)
{
    const float* x = nullptr; const float* W = nullptr; const float* b = nullptr;
    for (int i = 0; i < n_in; ++i) {
        if      (in_sizes[i] == NBAT * NINP) x = (const float*)d_in[i];
        else if (in_sizes[i] == NN * NN)     W = (const float*)d_in[i];
        else if (in_sizes[i] == NN)          b = (const float*)d_in[i];
    }

    build_csr<<<(NN - NINP) / 8, 256>>>(W, b);
    build_compact<<<NBLK, 32>>>();
    build_levels<<<16, 32>>>();

    int smem_bytes = 226960;
    cudaFuncSetAttribute(dagnn_main,
                         cudaFuncAttributeMaxDynamicSharedMemorySize, smem_bytes);
    dagnn_main<<<NBAT / 64, THREADS, smem_bytes>>>(x, (float*)d_out);
}

// round 12
// speedup vs baseline: 1.3388x; 1.1017x over previous
#include <cuda_runtime.h>
#include <cstdint>

#define NN     1024
#define NINP   256
#define NOUTP  256
#define NBAT   8192
#define MAXFS  96      // per-row far cap (smem staging)
#define IMAX   12      // intra cap per row
#define CAP    1536    // compact pairs per 32-row block (mean ~1150, >10 sigma)
#define NBLK   24
#define THREADS 512

__device__ int2 g_intra[NN * IMAX];
__device__ int2 g_meta [NN];           // {far count, bits(bias)}
__device__ int  g_icnt [NN];
__device__ int2 g_cpack[NBLK * CAP];   // compact per-block far stream (even-aligned rows)
__device__ int  g_coff [NBLK * 33];    // per-block row offsets (even) + total
__device__ int  g_ord  [16 * 32];      // node | (icnt<<8), level-sorted
__device__ int  g_lst  [16 * 34];      // level starts (sentinel 32)

// ============================================================================
// Fused build: one CTA per 32-row node block. Scan rows (float4, row-bounded),
// split far/intra, smem-stage far, prefix (even-padded), copy to compact.
// ============================================================================
__global__ void build_all(const float* __restrict__ W, const float* __restrict__ b)
{
    __shared__ int2 sfar[32 * MAXFS];   // 24576 B
    __shared__ int  scnt[32];
    __shared__ int  soff[33];

    int blk  = blockIdx.x;
    int base = NINP + blk * 32;
    int tid = threadIdx.x, w = tid >> 5, lane = tid & 31;
    bool isOut = (blk >= 16);
    unsigned lt = (1u << lane) - 1u;

    #pragma unroll
    for (int r = 0; r < 4; ++r) {
        int n   = w * 4 + r;
        int row = base + n;
        int fb  = isOut ? NN : base;
        int m4max = (row + 127) >> 7;
        int fc = 0, ic = 0;
        const float4* wr = reinterpret_cast<const float4*>(W + (size_t)row * NN);
        for (int m = 0; m < m4max; ++m) {
            float4 v = __ldg(wr + m * 32 + lane);
            int c0 = m * 128 + lane * 4;
            #pragma unroll
            for (int q = 0; q < 4; ++q) {
                float wv = (q == 0) ? v.x : (q == 1) ? v.y : (q == 2) ? v.z : v.w;
                int col = c0 + q;
                bool nz = (wv != 0.0f);
                unsigned bf = __ballot_sync(~0u, nz && col <  fb);
                unsigned bi = __ballot_sync(~0u, nz && col >= fb);
                if (nz) {
                    if (col < fb) {
                        int p = fc + __popc(bf & lt);
                        if (p < MAXFS) sfar[n * MAXFS + p] = make_int2(col * 33, __float_as_int(wv));
                    } else {
                        int p = ic + __popc(bi & lt);
                        if (p < IMAX) g_intra[(size_t)row * IMAX + p] = make_int2(col * 33, __float_as_int(wv));
                    }
                }
                fc += __popc(bf); ic += __popc(bi);
            }
        }
        if (lane == 0) {
            int fcl = fc < MAXFS ? fc : MAXFS;
            scnt[n] = fcl;
            g_meta[row] = make_int2(fcl, __float_as_int(__ldg(&b[row])));
            g_icnt[row] = ic < IMAX ? ic : IMAX;
        }
    }
    __syncthreads();

    // warp 0: exclusive prefix over even-padded counts
    if (w == 0) {
        int cnt  = scnt[lane];
        int cnt2 = (cnt + 1) & ~1;
        int v = cnt2;
        #pragma unroll
        for (int d = 1; d < 32; d <<= 1) {
            int t = __shfl_up_sync(~0u, v, d);
            if (lane >= d) v += t;
        }
        int excl = v - cnt2;
        soff[lane] = excl;
        g_coff[blk * 33 + lane] = excl;
        if (lane == 31) { soff[32] = v; g_coff[blk * 33 + 32] = v; }
    }
    __syncthreads();

    // copy rows to compact stream; zero-pad odd rows to even
    for (int n = w; n < 32; n += 8) {
        int off = soff[n], cnt = scnt[n];
        int2* dst = g_cpack + (size_t)blk * CAP + off;
        for (int t = lane; t < cnt; t += 32) dst[t] = sfar[n * MAXFS + t];
        if (lane == 0 && (cnt & 1)) dst[cnt] = make_int2(0, 0);
    }
}

// ============================================================================
// Levels per hidden block (intra-only deps).
// ============================================================================
__global__ void build_levels()
{
    int blk = blockIdx.x, n = threadIdx.x;
    int base = NINP + blk * 32;
    int row = base + n;
    int ic = g_icnt[row];
    unsigned mymask = 0;
    for (int s = 0; s < ic; ++s) {
        int d = g_intra[(size_t)row * IMAX + s].x / 33 - base;
        if (d >= 0) mymask |= 1u << d;
    }
    int lvl = -1;
    unsigned done = 0;
    for (int it = 0; it < 32; ++it) {
        bool rdy = (lvl < 0) && ((mymask & ~done) == 0);
        unsigned bal = __ballot_sync(~0u, rdy);
        if (rdy) lvl = it;
        done |= bal;
        if (done == 0xffffffffu) break;
    }
    unsigned lt = (1u << n) - 1u;
    int run = 0, pos = 0;
    for (int L = 0; L < 32; ++L) {
        unsigned bal = __ballot_sync(~0u, lvl == L);
        if (lvl == L) pos = run + __popc(bal & lt);
        if (n == 0 && L < 34) g_lst[blk * 34 + L] = (run < 32) ? run : 32;
        run += __popc(bal);
    }
    if (n < 2) g_lst[blk * 34 + 32 + n] = 32;
    g_ord[blk * 32 + pos] = n | (ic << 8);
}

// ============================================================================
// Main. smem (bytes):
//   z2     float2[768][33] @0        202752
//   acc    float2[32*33]   @202752     8448
//   cpairs int2[1536]      @211200    12288
//   coff   int[33]         @223488      136
//   ipb    int2[32*12]     @223624     3072
//   sord   int[32]         @226696      128
//   slst   int[34]         @226824      136    total 226960
// ============================================================================
extern __shared__ char smraw[];

__device__ __forceinline__ float tanhfast(float v) {
    float e = __expf(v + v);
    return 1.0f - __fdividef(2.0f, e + 1.0f);
}

__global__ void __launch_bounds__(THREADS, 1)
dagnn_main(const float* __restrict__ x, float* __restrict__ out)
{
    float2* z2    = (float2*)smraw;
    float2* acc   = (float2*)(smraw + 202752);
    int2*   cpair = (int2*)  (smraw + 211200);
    int*    coff  = (int*)   (smraw + 223488);
    int2*   ipb   = (int2*)  (smraw + 223624);
    int*    sord  = (int*)   (smraw + 226696);
    int*    slst  = (int*)   (smraw + 226824);

    int tid = threadIdx.x, w = tid >> 5, lane = tid & 31;
    int b0 = blockIdx.x * 64;
    float* zf = (float*)z2;

    int2 p0, p1, p2, ib;
    int  aux = 0;

    // prefetch block 0
    {
        const int2* cp = g_cpack;
        p0 = __ldg(cp + tid); p1 = __ldg(cp + 512 + tid); p2 = __ldg(cp + 1024 + tid);
        if (tid < 384)            ib  = __ldg(&g_intra[(size_t)NINP * IMAX + tid]);
        else if (tid < 416)       aux = __ldg(&g_ord[tid - 384]);
        else if (tid < 450)       aux = __ldg(&g_lst[tid - 416]);
        else if (tid < 483)       aux = __ldg(&g_coff[tid - 450]);
    }

    // fill z2 with inputs
    #pragma unroll
    for (int it = 0; it < 32; ++it) {
        int t = tid + it * THREADS;
        int n = t & 255, c = t >> 8;
        zf[n * 66 + c] = x[(size_t)(b0 + c) * NINP + n];
    }

    for (int k = 0; k < NBLK; ++k) {
        bool hid = (k < 16);
        int base = NINP + k * 32;

        // commit staged data for block k
        __syncthreads();
        cpair[tid] = p0; cpair[512 + tid] = p1; cpair[1024 + tid] = p2;
        if (tid < 384)      { if (hid) ipb[tid] = ib; }
        else if (tid < 416) { if (hid) sord[tid - 384] = aux; }
        else if (tid < 450) { if (hid) slst[tid - 416] = aux; }
        else if (tid < 483) { coff[tid - 450] = aux; }
        __syncthreads();

        // prefetch block k+1
        if (k + 1 < NBLK) {
            int nb = k + 1;
            bool nhid = (nb < 16);
            const int2* cp = g_cpack + (size_t)nb * CAP;
            p0 = __ldg(cp + tid); p1 = __ldg(cp + 512 + tid); p2 = __ldg(cp + 1024 + tid);
            if (tid < 384)      { if (nhid) ib  = __ldg(&g_intra[(size_t)(NINP + nb*32) * IMAX + tid]); }
            else if (tid < 416) { if (nhid) aux = __ldg(&g_ord[nb * 32 + tid - 384]); }
            else if (tid < 450) { if (nhid) aux = __ldg(&g_lst[nb * 34 + tid - 416]); }
            else if (tid < 483) { aux = __ldg(&g_coff[nb * 33 + tid - 450]); }
        }

        // far phase: warp w -> rows 2w, 2w+1; even-aligned int4 pair loads
        #pragma unroll
        for (int rr = 0; rr < 2; ++rr) {
            int n = 2 * w + rr;
            int row = base + n;
            int bb = __ldg(&g_meta[row]).y;
            int s = coff[n], e = coff[n + 1];         // both even
            const int4* p4 = (const int4*)cpair + (s >> 1);
            int m = (e - s) >> 1;                      // int4 groups (2 pairs)
            float a0 = 0.f, a1 = 0.f, c0 = 0.f, c1 = 0.f;
            #pragma unroll 4
            for (int j = 0; j < m; ++j) {
                int4 q = p4[j];
                float2 za = z2[q.x + lane];
                float2 zb = z2[q.z + lane];
                float w0 = __int_as_float(q.y), w1 = __int_as_float(q.w);
                a0 = fmaf(w0, za.x, a0); c0 = fmaf(w0, za.y, c0);
                a1 = fmaf(w1, zb.x, a1); c1 = fmaf(w1, zb.y, c1);
            }
            float bias = __int_as_float(bb);
            acc[n * 33 + lane] = make_float2(bias + a0 + a1, bias + c0 + c1);
        }
        __syncthreads();

        if (hid) {
            for (int L = 0; slst[L] < 32; ++L) {
                for (int j = slst[L] + w; j < slst[L + 1]; j += 16) {
                    int oi = sord[j];
                    int n  = oi & 255;
                    int ic = oi >> 8;
                    float2 v = acc[n * 33 + lane];
                    const int2* q = ipb + n * IMAX;
                    for (int s = 0; s < ic; ++s) {
                        int2 p = q[s];
                        float2 zz = z2[p.x + lane];
                        float wv = __int_as_float(p.y);
                        v.x = fmaf(wv, zz.x, v.x);
                        v.y = fmaf(wv, zz.y, v.y);
                    }
                    z2[(base + n) * 33 + lane] = make_float2(tanhfast(v.x), tanhfast(v.y));
                }
                __syncthreads();
            }
        } else {
            int goff = (k - 16) * 32;
            const float* af = (const float*)acc;
            #pragma unroll
            for (int cc = 0; cc < 4; ++cc) {
                int c = w * 4 + cc;
                out[(size_t)(b0 + c) * NOUTP + goff + lane] = af[lane * 66 + c];
            }
            __syncthreads();
        }
    }
}

// ============================================================================
extern "C" void kernel_launch(void* const* d_in, const int* in_sizes, int n_in,
                              void* d_out, int out_size)
{
    const float* x = nullptr; const float* W = nullptr; const float* b = nullptr;
    for (int i = 0; i < n_in; ++i) {
        if      (in_sizes[i] == NBAT * NINP) x = (const float*)d_in[i];
        else if (in_sizes[i] == NN * NN)     W = (const float*)d_in[i];
        else if (in_sizes[i] == NN)          b = (const float*)d_in[i];
    }

    build_all<<<NBLK, 256>>>(W, b);
    build_levels<<<16, 32>>>();

    int smem_bytes = 226960;
    cudaFuncSetAttribute(dagnn_main,
                         cudaFuncAttributeMaxDynamicSharedMemorySize, smem_bytes);
    dagnn_main<<<NBAT / 64, THREADS, smem_bytes>>>(x, (float*)d_out);
}

// round 14
// speedup vs baseline: 1.4502x; 1.0831x over previous
#include <cuda_runtime.h>
#include <cstdint>

#define NN     1024
#define NINP   256
#define NOUTP  256
#define NBAT   8192
#define MAXF   96      // padded per-row far cap (staging)
#define IMAX   12      // intra cap per row
#define CAP    1536    // compact pairs per 32-row block (mean ~1230 even-padded)
#define NBLK   24
#define THREADS 512

__device__ int2 g_farp [NN * MAXF];    // padded per-row far pairs
__device__ int2 g_intra[NN * IMAX];
__device__ int2 g_meta [NN];           // {far count, bits(bias)}
__device__ int  g_icnt [NN];
__device__ int2 g_cpack[NBLK * CAP];   // compact per-block far stream (even rows)
__device__ int  g_coff [NBLK * 33];
__device__ int  g_ord  [16 * 32];
__device__ int  g_lst  [16 * 34];

// ============================================================================
// Build 1: wide W scan. 192 CTAs x 128 thr, one warp per row.
// far = col < (row & ~31) [hidden] / all cols [output]; intra = rest.
// ============================================================================
__global__ void build_split(const float* __restrict__ W, const float* __restrict__ b)
{
    int row  = NINP + blockIdx.x * 4 + (threadIdx.x >> 5);
    int lane = threadIdx.x & 31;
    int fb   = (row >= NN - NOUTP) ? NN : (row & ~31);
    int m4max = (row + 127) >> 7;
    int fc = 0, ic = 0;
    unsigned lt = (1u << lane) - 1u;
    const float4* wr = reinterpret_cast<const float4*>(W + (size_t)row * NN);
    for (int m = 0; m < m4max; ++m) {
        float4 v = __ldg(wr + m * 32 + lane);
        int c0 = m * 128 + lane * 4;
        #pragma unroll
        for (int q = 0; q < 4; ++q) {
            float wv = (q == 0) ? v.x : (q == 1) ? v.y : (q == 2) ? v.z : v.w;
            int col = c0 + q;
            bool nz = (wv != 0.0f);
            unsigned bf = __ballot_sync(~0u, nz && col <  fb);
            unsigned bi = __ballot_sync(~0u, nz && col >= fb);
            if (nz) {
                if (col < fb) {
                    int p = fc + __popc(bf & lt);
                    if (p < MAXF) g_farp[(size_t)row * MAXF + p] = make_int2(col * 33, __float_as_int(wv));
                } else {
                    int p = ic + __popc(bi & lt);
                    if (p < IMAX) g_intra[(size_t)row * IMAX + p] = make_int2(col * 33, __float_as_int(wv));
                }
            }
            fc += __popc(bf); ic += __popc(bi);
        }
    }
    if (lane == 0) {
        g_meta[row] = make_int2(fc < MAXF ? fc : MAXF, __float_as_int(__ldg(&b[row])));
        g_icnt[row] = ic < IMAX ? ic : IMAX;
    }
}

// ============================================================================
// Build 2: compaction. 24 CTAs x 256 thr (8 warps copy 4 rows each).
// Rows even-padded with a {0,0} pair so the consumer can use int4 loads.
// ============================================================================
__global__ void build_compact()
{
    __shared__ int soff[33];
    __shared__ int scnt[32];

    int blk  = blockIdx.x;
    int base = NINP + blk * 32;
    int tid = threadIdx.x, w = tid >> 5, lane = tid & 31;

    if (w == 0) {
        int cnt  = g_meta[base + lane].x;
        scnt[lane] = cnt;
        int cnt2 = (cnt + 1) & ~1;
        int v = cnt2;
        #pragma unroll
        for (int d = 1; d < 32; d <<= 1) {
            int t = __shfl_up_sync(~0u, v, d);
            if (lane >= d) v += t;
        }
        int excl = v - cnt2;
        soff[lane] = excl;
        g_coff[blk * 33 + lane] = excl;
        if (lane == 31) { soff[32] = v < CAP ? v : CAP; g_coff[blk * 33 + 32] = soff[32]; }
    }
    __syncthreads();

    #pragma unroll
    for (int r = 0; r < 4; ++r) {
        int n = w + 8 * r;
        int off = soff[n], cnt = scnt[n];
        if (off + cnt > CAP) cnt = (CAP - off > 0) ? CAP - off : 0;
        const int2* src = g_farp + (size_t)(base + n) * MAXF;
        int2* dst = g_cpack + (size_t)blk * CAP + off;
        for (int t = lane; t < cnt; t += 32) dst[t] = src[t];
        if (lane == 0 && (cnt & 1)) dst[cnt] = make_int2(0, 0);
    }
}

// ============================================================================
// Build 3: dependency levels per hidden block (intra-only deps).
// ============================================================================
__global__ void build_levels()
{
    int blk = blockIdx.x, n = threadIdx.x;
    int base = NINP + blk * 32;
    int row = base + n;
    int ic = g_icnt[row];
    unsigned mymask = 0;
    for (int s = 0; s < ic; ++s) {
        int d = g_intra[(size_t)row * IMAX + s].x / 33 - base;
        if (d >= 0) mymask |= 1u << d;
    }
    int lvl = -1;
    unsigned done = 0;
    for (int it = 0; it < 32; ++it) {
        bool rdy = (lvl < 0) && ((mymask & ~done) == 0);
        unsigned bal = __ballot_sync(~0u, rdy);
        if (rdy) lvl = it;
        done |= bal;
        if (done == 0xffffffffu) break;
    }
    unsigned lt = (1u << n) - 1u;
    int run = 0, pos = 0;
    for (int L = 0; L < 32; ++L) {
        unsigned bal = __ballot_sync(~0u, lvl == L);
        if (lvl == L) pos = run + __popc(bal & lt);
        if (n == 0 && L < 34) g_lst[blk * 34 + L] = (run < 32) ? run : 32;
        run += __popc(bal);
    }
    if (n < 2) g_lst[blk * 34 + 32 + n] = 32;
    g_ord[blk * 32 + pos] = n | (ic << 8);
}

// ============================================================================
// Main (unchanged from R12 fast path).
// ============================================================================
extern __shared__ char smraw[];

__device__ __forceinline__ float tanhfast(float v) {
    float e = __expf(v + v);
    return 1.0f - __fdividef(2.0f, e + 1.0f);
}

__global__ void __launch_bounds__(THREADS, 1)
dagnn_main(const float* __restrict__ x, float* __restrict__ out)
{
    float2* z2    = (float2*)smraw;
    float2* acc   = (float2*)(smraw + 202752);
    int2*   cpair = (int2*)  (smraw + 211200);
    int*    coff  = (int*)   (smraw + 223488);
    int2*   ipb   = (int2*)  (smraw + 223624);
    int*    sord  = (int*)   (smraw + 226696);
    int*    slst  = (int*)   (smraw + 226824);

    int tid = threadIdx.x, w = tid >> 5, lane = tid & 31;
    int b0 = blockIdx.x * 64;
    float* zf = (float*)z2;

    int2 p0, p1, p2, ib;
    int  aux = 0;

    {
        const int2* cp = g_cpack;
        p0 = __ldg(cp + tid); p1 = __ldg(cp + 512 + tid); p2 = __ldg(cp + 1024 + tid);
        if (tid < 384)            ib  = __ldg(&g_intra[(size_t)NINP * IMAX + tid]);
        else if (tid < 416)       aux = __ldg(&g_ord[tid - 384]);
        else if (tid < 450)       aux = __ldg(&g_lst[tid - 416]);
        else if (tid < 483)       aux = __ldg(&g_coff[tid - 450]);
    }

    #pragma unroll
    for (int it = 0; it < 32; ++it) {
        int t = tid + it * THREADS;
        int n = t & 255, c = t >> 8;
        zf[n * 66 + c] = x[(size_t)(b0 + c) * NINP + n];
    }

    for (int k = 0; k < NBLK; ++k) {
        bool hid = (k < 16);
        int base = NINP + k * 32;

        __syncthreads();
        cpair[tid] = p0; cpair[512 + tid] = p1; cpair[1024 + tid] = p2;
        if (tid < 384)      { if (hid) ipb[tid] = ib; }
        else if (tid < 416) { if (hid) sord[tid - 384] = aux; }
        else if (tid < 450) { if (hid) slst[tid - 416] = aux; }
        else if (tid < 483) { coff[tid - 450] = aux; }
        __syncthreads();

        if (k + 1 < NBLK) {
            int nb = k + 1;
            bool nhid = (nb < 16);
            const int2* cp = g_cpack + (size_t)nb * CAP;
            p0 = __ldg(cp + tid); p1 = __ldg(cp + 512 + tid); p2 = __ldg(cp + 1024 + tid);
            if (tid < 384)      { if (nhid) ib  = __ldg(&g_intra[(size_t)(NINP + nb*32) * IMAX + tid]); }
            else if (tid < 416) { if (nhid) aux = __ldg(&g_ord[nb * 32 + tid - 384]); }
            else if (tid < 450) { if (nhid) aux = __ldg(&g_lst[nb * 34 + tid - 416]); }
            else if (tid < 483) { aux = __ldg(&g_coff[nb * 33 + tid - 450]); }
        }

        #pragma unroll
        for (int rr = 0; rr < 2; ++rr) {
            int n = 2 * w + rr;
            int row = base + n;
            int bb = __ldg(&g_meta[row]).y;
            int s = coff[n], e = coff[n + 1];
            const int4* p4 = (const int4*)cpair + (s >> 1);
            int m = (e - s) >> 1;
            float a0 = 0.f, a1 = 0.f, c0 = 0.f, c1 = 0.f;
            #pragma unroll 4
            for (int j = 0; j < m; ++j) {
                int4 q = p4[j];
                float2 za = z2[q.x + lane];
                float2 zb = z2[q.z + lane];
                float w0 = __int_as_float(q.y), w1 = __int_as_float(q.w);
                a0 = fmaf(w0, za.x, a0); c0 = fmaf(w0, za.y, c0);
                a1 = fmaf(w1, zb.x, a1); c1 = fmaf(w1, zb.y, c1);
            }
            float bias = __int_as_float(bb);
            acc[n * 33 + lane] = make_float2(bias + a0 + a1, bias + c0 + c1);
        }
        __syncthreads();

        if (hid) {
            for (int L = 0; slst[L] < 32; ++L) {
                for (int j = slst[L] + w; j < slst[L + 1]; j += 16) {
                    int oi = sord[j];
                    int n  = oi & 255;
                    int ic = oi >> 8;
                    float2 v = acc[n * 33 + lane];
                    const int2* q = ipb + n * IMAX;
                    for (int s = 0; s < ic; ++s) {
                        int2 p = q[s];
                        float2 zz = z2[p.x + lane];
                        float wv = __int_as_float(p.y);
                        v.x = fmaf(wv, zz.x, v.x);
                        v.y = fmaf(wv, zz.y, v.y);
                    }
                    z2[(base + n) * 33 + lane] = make_float2(tanhfast(v.x), tanhfast(v.y));
                }
                __syncthreads();
            }
        } else {
            int goff = (k - 16) * 32;
            const float* af = (const float*)acc;
            #pragma unroll
            for (int cc = 0; cc < 4; ++cc) {
                int c = w * 4 + cc;
                out[(size_t)(b0 + c) * NOUTP + goff + lane] = af[lane * 66 + c];
            }
            __syncthreads();
        }
    }
}

// ============================================================================
extern "C" void kernel_launch(void* const* d_in, const int* in_sizes, int n_in,
                              void* d_out, int out_size)
{
    const float* x = nullptr; const float* W = nullptr; const float* b = nullptr;
    for (int i = 0; i < n_in; ++i) {
        if      (in_sizes[i] == NBAT * NINP) x = (const float*)d_in[i];
        else if (in_sizes[i] == NN * NN)     W = (const float*)d_in[i];
        else if (in_sizes[i] == NN)          b = (const float*)d_in[i];
    }

    build_split<<<(NN - NINP) / 4, 128>>>(W, b);
    build_compact<<<NBLK, 256>>>();
    build_levels<<<16, 32>>>();

    int smem_bytes = 226960;
    cudaFuncSetAttribute(dagnn_main,
                         cudaFuncAttributeMaxDynamicSharedMemorySize, smem_bytes);
    dagnn_main<<<NBAT / 64, THREADS, smem_bytes>>>(x, (float*)d_out);
}

// round 15
// speedup vs baseline: 1.5211x; 1.0489x over previous
#include <cuda_runtime.h>
#include <cuda_fp16.h>
#include <cstdint>

#define NN     1024
#define NINP   256
#define NOUTP  256
#define NBAT   8192
#define MAXF   96
#define IMAX   12
#define CAP    1536
#define NBLK   24
#define THREADS 512

__device__ int2 g_farp [NN * MAXF];
__device__ int2 g_intra[NN * IMAX];
__device__ int2 g_meta [NN];           // {far count, bits(bias)}
__device__ int  g_icnt [NN];
__device__ int2 g_cpack[NBLK * CAP];
__device__ int  g_coff [NBLK * 33];
__device__ int  g_ord  [16 * 32];
__device__ int  g_lst  [16 * 34];

// ============================================================================
// Build 1: wide W scan. 192 CTAs x 128 thr, one warp per row.
// ============================================================================
__global__ void build_split(const float* __restrict__ W, const float* __restrict__ b)
{
    int row  = NINP + blockIdx.x * 4 + (threadIdx.x >> 5);
    int lane = threadIdx.x & 31;
    int fb   = (row >= NN - NOUTP) ? NN : (row & ~31);
    int m4max = (row + 127) >> 7;
    int fc = 0, ic = 0;
    unsigned lt = (1u << lane) - 1u;
    const float4* wr = reinterpret_cast<const float4*>(W + (size_t)row * NN);
    for (int m = 0; m < m4max; ++m) {
        float4 v = __ldg(wr + m * 32 + lane);
        int c0 = m * 128 + lane * 4;
        #pragma unroll
        for (int q = 0; q < 4; ++q) {
            float wv = (q == 0) ? v.x : (q == 1) ? v.y : (q == 2) ? v.z : v.w;
            int col = c0 + q;
            bool nz = (wv != 0.0f);
            unsigned bf = __ballot_sync(~0u, nz && col <  fb);
            unsigned bi = __ballot_sync(~0u, nz && col >= fb);
            if (nz) {
                if (col < fb) {
                    int p = fc + __popc(bf & lt);
                    if (p < MAXF) g_farp[(size_t)row * MAXF + p] = make_int2(col * 33, __float_as_int(wv));
                } else {
                    int p = ic + __popc(bi & lt);
                    if (p < IMAX) g_intra[(size_t)row * IMAX + p] = make_int2(col * 33, __float_as_int(wv));
                }
            }
            fc += __popc(bf); ic += __popc(bi);
        }
    }
    if (lane == 0) {
        g_meta[row] = make_int2(fc < MAXF ? fc : MAXF, __float_as_int(__ldg(&b[row])));
        g_icnt[row] = ic < IMAX ? ic : IMAX;
    }
}

// ============================================================================
// Build 2: compaction, even-padded rows. 24 CTAs x 256 thr.
// ============================================================================
__global__ void build_compact()
{
    __shared__ int soff[33];
    __shared__ int scnt[32];

    int blk  = blockIdx.x;
    int base = NINP + blk * 32;
    int tid = threadIdx.x, w = tid >> 5, lane = tid & 31;

    if (w == 0) {
        int cnt  = g_meta[base + lane].x;
        scnt[lane] = cnt;
        int cnt2 = (cnt + 1) & ~1;
        int v = cnt2;
        #pragma unroll
        for (int d = 1; d < 32; d <<= 1) {
            int t = __shfl_up_sync(~0u, v, d);
            if (lane >= d) v += t;
        }
        int excl = v - cnt2;
        soff[lane] = excl;
        g_coff[blk * 33 + lane] = excl;
        if (lane == 31) { soff[32] = v < CAP ? v : CAP; g_coff[blk * 33 + 32] = soff[32]; }
    }
    __syncthreads();

    #pragma unroll
    for (int r = 0; r < 4; ++r) {
        int n = w + 8 * r;
        int off = soff[n], cnt = scnt[n];
        if (off + cnt > CAP) cnt = (CAP - off > 0) ? CAP - off : 0;
        const int2* src = g_farp + (size_t)(base + n) * MAXF;
        int2* dst = g_cpack + (size_t)blk * CAP + off;
        for (int t = lane; t < cnt; t += 32) dst[t] = src[t];
        if (lane == 0 && (cnt & 1)) dst[cnt] = make_int2(0, 0);
    }
}

// ============================================================================
// Build 3: levels per hidden block.
// ============================================================================
__global__ void build_levels()
{
    int blk = blockIdx.x, n = threadIdx.x;
    int base = NINP + blk * 32;
    int row = base + n;
    int ic = g_icnt[row];
    unsigned mymask = 0;
    for (int s = 0; s < ic; ++s) {
        int d = g_intra[(size_t)row * IMAX + s].x / 33 - base;
        if (d >= 0) mymask |= 1u << d;
    }
    int lvl = -1;
    unsigned done = 0;
    for (int it = 0; it < 32; ++it) {
        bool rdy = (lvl < 0) && ((mymask & ~done) == 0);
        unsigned bal = __ballot_sync(~0u, rdy);
        if (rdy) lvl = it;
        done |= bal;
        if (done == 0xffffffffu) break;
    }
    unsigned lt = (1u << n) - 1u;
    int run = 0, pos = 0;
    for (int L = 0; L < 32; ++L) {
        unsigned bal = __ballot_sync(~0u, lvl == L);
        if (lvl == L) pos = run + __popc(bal & lt);
        if (n == 0 && L < 34) g_lst[blk * 34 + L] = (run < 32) ? run : 32;
        run += __popc(bal);
    }
    if (n < 2) g_lst[blk * 34 + 32 + n] = 32;
    g_ord[blk * 32 + pos] = n | (ic << 8);
}

// ============================================================================
// Main. z stored as half2 (2 batch cols per lane), fp32 accumulation.
// smem (bytes):
//   zh    half2[768*33]  @0        101376
//   acc   float2[32*33]  @101376     8448
//   cpair int2[1536]     @109824    12288
//   coff  int[33]        @122112      136
//   ipb   int2[32*12]    @122248     3072
//   sord  int[32]        @125320      128
//   slst  int[34]        @125448      136    total 125584
// ============================================================================
extern __shared__ char smraw[];

__device__ __forceinline__ float tanhfast(float v) {
    float e = __expf(v + v);
    return 1.0f - __fdividef(2.0f, e + 1.0f);
}

__global__ void __launch_bounds__(THREADS, 1)
dagnn_main(const float* __restrict__ x, float* __restrict__ out)
{
    __half2* zh   = (__half2*)smraw;
    float2*  acc  = (float2*)(smraw + 101376);
    int2*   cpair = (int2*)  (smraw + 109824);
    int*    coff  = (int*)   (smraw + 122112);
    int2*   ipb   = (int2*)  (smraw + 122248);
    int*    sord  = (int*)   (smraw + 125320);
    int*    slst  = (int*)   (smraw + 125448);

    int tid = threadIdx.x, w = tid >> 5, lane = tid & 31;
    int b0 = blockIdx.x * 64;
    __half* zhf = (__half*)zh;

    int2 p0, p1, p2, ib;
    int  aux = 0;

    // prefetch block 0 staged data
    {
        const int2* cp = g_cpack;
        p0 = __ldg(cp + tid); p1 = __ldg(cp + 512 + tid); p2 = __ldg(cp + 1024 + tid);
        if (tid < 384)            ib  = __ldg(&g_intra[(size_t)NINP * IMAX + tid]);
        else if (tid < 416)       aux = __ldg(&g_ord[tid - 384]);
        else if (tid < 450)       aux = __ldg(&g_lst[tid - 416]);
        else if (tid < 483)       aux = __ldg(&g_coff[tid - 450]);
    }

    // fill z with inputs (coalesced LDG -> half STS)
    #pragma unroll
    for (int it = 0; it < 32; ++it) {
        int t = tid + it * THREADS;
        int n = t & 255, c = t >> 8;
        zhf[n * 66 + c] = __float2half(x[(size_t)(b0 + c) * NINP + n]);
    }

    for (int k = 0; k < NBLK; ++k) {
        bool hid = (k < 16);
        int base = NINP + k * 32;

        // commit staged data for block k
        __syncthreads();
        cpair[tid] = p0; cpair[512 + tid] = p1; cpair[1024 + tid] = p2;
        if (tid < 384)      { if (hid) ipb[tid] = ib; }
        else if (tid < 416) { if (hid) sord[tid - 384] = aux; }
        else if (tid < 450) { if (hid) slst[tid - 416] = aux; }
        else if (tid < 483) { coff[tid - 450] = aux; }
        __syncthreads();

        // prefetch block k+1
        if (k + 1 < NBLK) {
            int nb = k + 1;
            bool nhid = (nb < 16);
            const int2* cp = g_cpack + (size_t)nb * CAP;
            p0 = __ldg(cp + tid); p1 = __ldg(cp + 512 + tid); p2 = __ldg(cp + 1024 + tid);
            if (tid < 384)      { if (nhid) ib  = __ldg(&g_intra[(size_t)(NINP + nb*32) * IMAX + tid]); }
            else if (tid < 416) { if (nhid) aux = __ldg(&g_ord[nb * 32 + tid - 384]); }
            else if (tid < 450) { if (nhid) aux = __ldg(&g_lst[nb * 34 + tid - 416]); }
            else if (tid < 483) { aux = __ldg(&g_coff[nb * 33 + tid - 450]); }
        }

        // far phase: warp w -> rows 2w, 2w+1
        #pragma unroll
        for (int rr = 0; rr < 2; ++rr) {
            int n = 2 * w + rr;
            int row = base + n;
            int bb = __ldg(&g_meta[row]).y;
            int s = coff[n], e = coff[n + 1];
            const int4* p4 = (const int4*)cpair + (s >> 1);
            int m = (e - s) >> 1;
            float a0 = 0.f, a1 = 0.f, c0 = 0.f, c1 = 0.f;
            #pragma unroll 4
            for (int j = 0; j < m; ++j) {
                int4 q = p4[j];
                float2 za = __half22float2(zh[q.x + lane]);
                float2 zb = __half22float2(zh[q.z + lane]);
                float w0 = __int_as_float(q.y), w1 = __int_as_float(q.w);
                a0 = fmaf(w0, za.x, a0); c0 = fmaf(w0, za.y, c0);
                a1 = fmaf(w1, zb.x, a1); c1 = fmaf(w1, zb.y, c1);
            }
            float bias = __int_as_float(bb);
            acc[n * 33 + lane] = make_float2(bias + a0 + a1, bias + c0 + c1);
        }
        __syncthreads();

        if (hid) {
            // level-parallel intra + tanh
            for (int L = 0; slst[L] < 32; ++L) {
                for (int j = slst[L] + w; j < slst[L + 1]; j += 16) {
                    int oi = sord[j];
                    int n  = oi & 255;
                    int ic = oi >> 8;
                    float2 v = acc[n * 33 + lane];
                    const int2* q = ipb + n * IMAX;
                    for (int s = 0; s < ic; ++s) {
                        int2 p = q[s];
                        float2 zz = __half22float2(zh[p.x + lane]);
                        float wv = __int_as_float(p.y);
                        v.x = fmaf(wv, zz.x, v.x);
                        v.y = fmaf(wv, zz.y, v.y);
                    }
                    zh[(base + n) * 33 + lane] = __floats2half2_rn(tanhfast(v.x), tanhfast(v.y));
                }
                __syncthreads();
            }
        } else {
            // output writeout from fp32 acc (full precision)
            int goff = (k - 16) * 32;
            const float* af = (const float*)acc;
            #pragma unroll
            for (int cc = 0; cc < 4; ++cc) {
                int c = w * 4 + cc;
                out[(size_t)(b0 + c) * NOUTP + goff + lane] = af[lane * 66 + c];
            }
            __syncthreads();
        }
    }
}

// ============================================================================
extern "C" void kernel_launch(void* const* d_in, const int* in_sizes, int n_in,
                              void* d_out, int out_size)
{
    const float* x = nullptr; const float* W = nullptr; const float* b = nullptr;
    for (int i = 0; i < n_in; ++i) {
        if      (in_sizes[i] == NBAT * NINP) x = (const float*)d_in[i];
        else if (in_sizes[i] == NN * NN)     W = (const float*)d_in[i];
        else if (in_sizes[i] == NN)          b = (const float*)d_in[i];
    }

    build_split<<<(NN - NINP) / 4, 128>>>(W, b);
    build_compact<<<NBLK, 256>>>();
    build_levels<<<16, 32>>>();

    int smem_bytes = 125584;
    cudaFuncSetAttribute(dagnn_main,
                         cudaFuncAttributeMaxDynamicSharedMemorySize, smem_bytes);
    dagnn_main<<<NBAT / 64, THREADS, smem_bytes>>>(x, (float*)d_out);
}

// round 16
// speedup vs baseline: 1.6353x; 1.0751x over previous
#include <cuda_runtime.h>
#include <cuda_fp16.h>
#include <cstdint>

#define NN     1024
#define NINP   256
#define NOUTP  256
#define NBAT   8192
#define MAXF   96
#define IMAX   12
#define CAP    1536
#define NBLK   24
#define THREADS 1024

__device__ int2 g_farp [NN * MAXF];
__device__ int2 g_intra[NN * IMAX];
__device__ int2 g_meta [NN];           // {far count, bits(bias)}
__device__ int  g_icnt [NN];
__device__ int2 g_cpack[NBLK * CAP];
__device__ int  g_coff [NBLK * 33];
__device__ int  g_rlvl [16 * 32];      // lvl | (icnt<<8) per hidden node
__device__ int  g_nlev [16];           // levels per hidden block

// ============================================================================
// Build 1: wide W scan. 192 CTAs x 128 thr, one warp per row.
// ============================================================================
__global__ void build_split(const float* __restrict__ W, const float* __restrict__ b)
{
    int row  = NINP + blockIdx.x * 4 + (threadIdx.x >> 5);
    int lane = threadIdx.x & 31;
    int fb   = (row >= NN - NOUTP) ? NN : (row & ~31);
    int m4max = (row + 127) >> 7;
    int fc = 0, ic = 0;
    unsigned lt = (1u << lane) - 1u;
    const float4* wr = reinterpret_cast<const float4*>(W + (size_t)row * NN);
    for (int m = 0; m < m4max; ++m) {
        float4 v = __ldg(wr + m * 32 + lane);
        int c0 = m * 128 + lane * 4;
        #pragma unroll
        for (int q = 0; q < 4; ++q) {
            float wv = (q == 0) ? v.x : (q == 1) ? v.y : (q == 2) ? v.z : v.w;
            int col = c0 + q;
            bool nz = (wv != 0.0f);
            unsigned bf = __ballot_sync(~0u, nz && col <  fb);
            unsigned bi = __ballot_sync(~0u, nz && col >= fb);
            if (nz) {
                if (col < fb) {
                    int p = fc + __popc(bf & lt);
                    if (p < MAXF) g_farp[(size_t)row * MAXF + p] = make_int2(col * 33, __float_as_int(wv));
                } else {
                    int p = ic + __popc(bi & lt);
                    if (p < IMAX) g_intra[(size_t)row * IMAX + p] = make_int2(col * 33, __float_as_int(wv));
                }
            }
            fc += __popc(bf); ic += __popc(bi);
        }
    }
    if (lane == 0) {
        g_meta[row] = make_int2(fc < MAXF ? fc : MAXF, __float_as_int(__ldg(&b[row])));
        g_icnt[row] = ic < IMAX ? ic : IMAX;
    }
}

// ============================================================================
// Build 2: compaction, even-padded rows. 24 CTAs x 256 thr.
// ============================================================================
__global__ void build_compact()
{
    __shared__ int soff[33];
    __shared__ int scnt[32];

    int blk  = blockIdx.x;
    int base = NINP + blk * 32;
    int tid = threadIdx.x, w = tid >> 5, lane = tid & 31;

    if (w == 0) {
        int cnt  = g_meta[base + lane].x;
        scnt[lane] = cnt;
        int cnt2 = (cnt + 1) & ~1;
        int v = cnt2;
        #pragma unroll
        for (int d = 1; d < 32; d <<= 1) {
            int t = __shfl_up_sync(~0u, v, d);
            if (lane >= d) v += t;
        }
        int excl = v - cnt2;
        soff[lane] = excl;
        g_coff[blk * 33 + lane] = excl;
        if (lane == 31) { soff[32] = v < CAP ? v : CAP; g_coff[blk * 33 + 32] = soff[32]; }
    }
    __syncthreads();

    #pragma unroll
    for (int r = 0; r < 4; ++r) {
        int n = w + 8 * r;
        int off = soff[n], cnt = scnt[n];
        if (off + cnt > CAP) cnt = (CAP - off > 0) ? CAP - off : 0;
        const int2* src = g_farp + (size_t)(base + n) * MAXF;
        int2* dst = g_cpack + (size_t)blk * CAP + off;
        for (int t = lane; t < cnt; t += 32) dst[t] = src[t];
        if (lane == 0 && (cnt & 1)) dst[cnt] = make_int2(0, 0);
    }
}

// ============================================================================
// Build 3: per-node level + per-block level count.
// ============================================================================
__global__ void build_levels()
{
    int blk = blockIdx.x, n = threadIdx.x;
    int base = NINP + blk * 32;
    int row = base + n;
    int ic = g_icnt[row];
    unsigned mymask = 0;
    for (int s = 0; s < ic; ++s) {
        int d = g_intra[(size_t)row * IMAX + s].x / 33 - base;
        if (d >= 0) mymask |= 1u << d;
    }
    int lvl = -1;
    unsigned done = 0;
    for (int it = 0; it < 32; ++it) {
        bool rdy = (lvl < 0) && ((mymask & ~done) == 0);
        unsigned bal = __ballot_sync(~0u, rdy);
        if (rdy) lvl = it;
        done |= bal;
        if (done == 0xffffffffu) break;
    }
    g_rlvl[blk * 32 + n] = lvl | (ic << 8);
    int m = lvl;
    #pragma unroll
    for (int d = 16; d; d >>= 1) m = max(m, __shfl_xor_sync(~0u, m, d));
    if (n == 0) g_nlev[blk] = m + 1;
}

// ============================================================================
// Main: 1024 threads (32 warps), one row per warp, acc in registers.
// smem (bytes):
//   zh    half2[768*33]  @0        101376
//   cpair int2[1536]     @101376    12288   (aliased as float st[32*66] in
//                                            output blocks, after far phase)
//   coff  int[33]        @113664      136
//   ipb   int2[32*12]    @113800     3072   total 116872
// ============================================================================
extern __shared__ char smraw[];

__device__ __forceinline__ float tanhfast(float v) {
    float e = __expf(v + v);
    return 1.0f - __fdividef(2.0f, e + 1.0f);
}

__global__ void __launch_bounds__(THREADS, 1)
dagnn_main(const float* __restrict__ x, float* __restrict__ out)
{
    __half2* zh   = (__half2*)smraw;
    int2*   cpair = (int2*)  (smraw + 101376);
    int*    coff  = (int*)   (smraw + 113664);
    int2*   ipb   = (int2*)  (smraw + 113800);
    float*  st    = (float*) (smraw + 101376);   // alias of cpair (output stage)

    int tid = threadIdx.x, w = tid >> 5, lane = tid & 31;
    int b0 = blockIdx.x * 64;
    __half* zhf = (__half*)zh;

    int2 p0, p1, ib;
    int  aux = 0;

    // prefetch block 0 staged data into registers
    {
        const int2* cp = g_cpack;
        p0 = __ldg(cp + tid);
        if (tid < 512)            p1 = __ldg(cp + 1024 + tid);
        if (tid < 384)            ib  = __ldg(&g_intra[(size_t)NINP * IMAX + tid]);
        else if (tid < 417)       aux = __ldg(&g_coff[tid - 384]);
    }

    // fill z with inputs (coalesced LDG -> half STS)
    #pragma unroll
    for (int it = 0; it < 16; ++it) {
        int t = tid + it * THREADS;
        int n = t & 255, c = t >> 8;
        zhf[n * 66 + c] = __float2half(x[(size_t)(b0 + c) * NINP + n]);
    }

    for (int k = 0; k < NBLK; ++k) {
        bool hid = (k < 16);
        int base = NINP + k * 32;

        // commit staged data for block k
        __syncthreads();                                    // barA
        cpair[tid] = p0;
        if (tid < 512)            cpair[1024 + tid] = p1;
        if (tid < 384)            { if (hid) ipb[tid] = ib; }
        else if (tid < 417)       coff[tid - 384] = aux;
        __syncthreads();                                    // barB

        // prefetch block k+1
        if (k + 1 < NBLK) {
            int nb = k + 1;
            bool nhid = (nb < 16);
            const int2* cp = g_cpack + (size_t)nb * CAP;
            p0 = __ldg(cp + tid);
            if (tid < 512)            p1 = __ldg(cp + 1024 + tid);
            if (tid < 384)            { if (nhid) ib = __ldg(&g_intra[(size_t)(NINP + nb*32) * IMAX + tid]); }
            else if (tid < 417)       aux = __ldg(&g_coff[nb * 33 + tid - 384]);
        }

        // per-warp metadata (uniform across lanes; latency hidden under far)
        int lvic = 0, nlev = 0;
        if (hid) { lvic = __ldg(&g_rlvl[k * 32 + w]); nlev = __ldg(&g_nlev[k]); }
        float bias = __int_as_float(__ldg(&g_meta[base + w]).y);

        // far phase: warp w computes row w; pairs from smem (even-aligned int4)
        int s = coff[w], e = coff[w + 1];
        const int4* p4 = (const int4*)cpair + (s >> 1);
        int m = (e - s) >> 1;
        float ax = 0.f, ay = 0.f, bx = 0.f, by = 0.f;
        #pragma unroll 4
        for (int j = 0; j < m; ++j) {
            int4 q = p4[j];
            float2 za = __half22float2(zh[q.x + lane]);
            float2 zb = __half22float2(zh[q.z + lane]);
            float w0 = __int_as_float(q.y), w1 = __int_as_float(q.w);
            ax = fmaf(w0, za.x, ax); ay = fmaf(w0, za.y, ay);
            bx = fmaf(w1, zb.x, bx); by = fmaf(w1, zb.y, by);
        }
        float vx = bias + ax + bx, vy = bias + ay + by;
        __syncthreads();                                    // barC

        if (hid) {
            int mylvl = lvic & 255, ic = lvic >> 8;
            for (int L = 0; L < nlev; ++L) {
                if (L == mylvl) {
                    const int2* q = ipb + w * IMAX;
                    for (int s2 = 0; s2 < ic; ++s2) {
                        int2 p = q[s2];
                        float2 zz = __half22float2(zh[p.x + lane]);
                        float wv = __int_as_float(p.y);
                        vx = fmaf(wv, zz.x, vx);
                        vy = fmaf(wv, zz.y, vy);
                    }
                    zh[(base + w) * 33 + lane] = __floats2half2_rn(tanhfast(vx), tanhfast(vy));
                }
                __syncthreads();
            }
        } else {
            // output block: stage acc to smem (cpair done being read), writeout
            *(float2*)&st[w * 66 + 2 * lane] = make_float2(vx, vy);
            __syncthreads();                                // barD
            int goff = (k - 16) * 32;
            #pragma unroll
            for (int cc = 0; cc < 2; ++cc) {
                int c = 2 * w + cc;
                out[(size_t)(b0 + c) * NOUTP + goff + lane] = st[lane * 66 + c];
            }
        }
    }
}

// ============================================================================
extern "C" void kernel_launch(void* const* d_in, const int* in_sizes, int n_in,
                              void* d_out, int out_size)
{
    const float* x = nullptr; const float* W = nullptr; const float* b = nullptr;
    for (int i = 0; i < n_in; ++i) {
        if      (in_sizes[i] == NBAT * NINP) x = (const float*)d_in[i];
        else if (in_sizes[i] == NN * NN)     W = (const float*)d_in[i];
        else if (in_sizes[i] == NN)          b = (const float*)d_in[i];
    }

    build_split<<<(NN - NINP) / 4, 128>>>(W, b);
    build_compact<<<NBLK, 256>>>();
    build_levels<<<16, 32>>>();

    int smem_bytes = 116872;
    cudaFuncSetAttribute(dagnn_main,
                         cudaFuncAttributeMaxDynamicSharedMemorySize, smem_bytes);
    dagnn_main<<<NBAT / 64, THREADS, smem_bytes>>>(x, (float*)d_out);
}